// round 7
// baseline (speedup 1.0000x reference)
#include <cuda_runtime.h>
#include <math.h>

// B=32, T=1024, C=1024, J=2048. One persistent kernel, 128 blocks x 512 thr.
// Phases per step: A (GEMM1 + fused LN-from-prev-step z-fill + out write)
//                  C (gelu-reduce + GEMM2 partial)
//                  D1 (parallel partial-reduce + LN statistics)
// 3 grid barriers/step. Scalar fp32 FFMA, 4j x 4b tile, conflict-free smem.

#define BB 32
#define CC 1024
#define TT 1024
#define NBLK 128

// ---- scratch ----
__device__ __align__(16) float g_yp[16][2048 * 32];   // GEMM1 partials [kc][j][b]
__device__ __align__(16) float g_y2p[32][BB * CC];    // GEMM2 partials [kc2][b][n]
__device__ __align__(16) float g_y2[BB * CC];         // reduced y2 [b][n]
__device__ float g_sum[BB][4];                        // per-b per-quarter sums
__device__ float g_sq[BB][4];                         // per-b per-quarter sums of squares

// ---- grid barrier ----
__device__ unsigned g_count = 0;
__device__ volatile unsigned g_gen = 0;

__device__ __forceinline__ void gbar() {
    __syncthreads();
    if (threadIdx.x == 0) {
        __threadfence();
        unsigned gen = g_gen;
        if (atomicAdd(&g_count, 1u) == NBLK - 1u) {
            atomicExch(&g_count, 0u);
            __threadfence();
            g_gen = gen + 1u;
        } else {
            while (g_gen == gen) { }
        }
        __threadfence();
    }
    __syncthreads();
}

// smem: zs [32][132] at 0 ; ws 2 x [32 k][264 j] at 4224 (k-major weight tiles)
#define WOFF 4224
#define WSTR (32 * 264)
#define SMEM_FLOATS (WOFF + 2 * WSTR)   // 21120 floats = 84480 B

// Inner GEMM, 256-j block tile, 32-K stages, double-buffered k-major weights.
// Thread (tx=tid&7, ty=tid>>3): j = base + ty*4 + jj, b = tx + 8q.
template <int NSTAGES, int ZSTR>
__device__ __forceinline__ void gemm_core(const float* __restrict__ wrow,
                                          float* sm, float acc[4][4],
                                          int tid, int tx, int ty) {
    float* zs = sm;
    float* wp = sm + WOFF;
    const int jf = tid & 255, kh = (tid >> 8) * 16;
    const float* wsrc = wrow + (size_t)jf * 2048 + kh;

#define WFILL(dst, a0, a1, a2, a3)                                        \
    {  float* wd_ = (dst) + kh * 264 + jf;                                \
       wd_[0*264]=a0.x;  wd_[1*264]=a0.y;  wd_[2*264]=a0.z;  wd_[3*264]=a0.w;  \
       wd_[4*264]=a1.x;  wd_[5*264]=a1.y;  wd_[6*264]=a1.z;  wd_[7*264]=a1.w;  \
       wd_[8*264]=a2.x;  wd_[9*264]=a2.y;  wd_[10*264]=a2.z; wd_[11*264]=a2.w; \
       wd_[12*264]=a3.x; wd_[13*264]=a3.y; wd_[14*264]=a3.z; wd_[15*264]=a3.w; }

    {   // stage 0 fill (transpose to k-major)
        float4 f0 = *(const float4*)(wsrc);
        float4 f1 = *(const float4*)(wsrc + 4);
        float4 f2 = *(const float4*)(wsrc + 8);
        float4 f3 = *(const float4*)(wsrc + 12);
        WFILL(wp, f0, f1, f2, f3);
    }
    __syncthreads();

    int buf = 0;
#pragma unroll 1
    for (int ks = 0; ks < NSTAGES; ks++) {
        float4 p0, p1, p2, p3;
        if (ks + 1 < NSTAGES) {
            const float* wn = wsrc + (ks + 1) * 32;
            p0 = *(const float4*)(wn);
            p1 = *(const float4*)(wn + 4);
            p2 = *(const float4*)(wn + 8);
            p3 = *(const float4*)(wn + 12);
        }
        const float* wb = wp + buf * WSTR + ty * 4;
        const float* zb = zs + tx * ZSTR + ks * 32;
#pragma unroll
        for (int kk = 0; kk < 8; kk++) {
            float4 wr[4], zr[4];
#pragma unroll
            for (int kq = 0; kq < 4; kq++)
                wr[kq] = *(const float4*)(wb + (kk * 4 + kq) * 264);
#pragma unroll
            for (int q = 0; q < 4; q++)
                zr[q] = *(const float4*)(zb + q * 8 * ZSTR + kk * 4);
#pragma unroll
            for (int kq = 0; kq < 4; kq++)
#pragma unroll
                for (int q = 0; q < 4; q++) {
                    float zk = (&zr[q].x)[kq];
                    acc[0][q] += wr[kq].x * zk;
                    acc[1][q] += wr[kq].y * zk;
                    acc[2][q] += wr[kq].z * zk;
                    acc[3][q] += wr[kq].w * zk;
                }
        }
        if (ks + 1 < NSTAGES) {
            WFILL(wp + (buf ^ 1) * WSTR, p0, p1, p2, p3);
        }
        __syncthreads();
        buf ^= 1;
    }
#undef WFILL
}

__global__ void __launch_bounds__(512, 1)
k_main(const float* __restrict__ x, const float* __restrict__ Wa,
       const float* __restrict__ ba, const float* __restrict__ Wb,
       const float* __restrict__ bb, const float* __restrict__ gamma,
       const float* __restrict__ beta, float* __restrict__ out) {
    extern __shared__ float sm[];
    __shared__ float smu[32], srs[32];
    __shared__ float red1[16], red2[16];
    const int bid = blockIdx.x, tid = threadIdx.x;
    const int tx = tid & 7, ty = tid >> 3;

    for (int t = 0; t < TT; t++) {
        // ===== Phase A: GEMM1 partial (8 jt x 16 kc) + fused LN z-fill + out =====
        {
            const int jt = bid & 7, kc = bid >> 3;
            if (t > 0 && kc < 8) {
                if (tid < 32) {
                    float s = 0.0f, s2 = 0.0f;
#pragma unroll
                    for (int q = 0; q < 4; q++) {
                        s  += __ldcg(&g_sum[tid][q]);
                        s2 += __ldcg(&g_sq[tid][q]);
                    }
                    float mu = s * (1.0f / 1024.0f);
                    float var = s2 * (1.0f / 1024.0f) - mu * mu;
                    smu[tid] = mu;
                    srs[tid] = rsqrtf(var + 1e-5f);
                }
                __syncthreads();
            }
            const int b = tid >> 4, k8 = (tid & 15) * 8;
            if (kc < 8) {
                const int c = kc * 128 + k8;
                if (t > 0) {
                    const float mu = smu[b], rs = srs[b];
                    float4 y0 = __ldcg((const float4*)&g_y2[b * CC + c]);
                    float4 y1 = __ldcg((const float4*)&g_y2[b * CC + c + 4]);
                    float4 ga0 = *(const float4*)(gamma + c);
                    float4 ga1 = *(const float4*)(gamma + c + 4);
                    float4 be0 = *(const float4*)(beta + c);
                    float4 be1 = *(const float4*)(beta + c + 4);
                    float4 h0, h1;
                    h0.x = (y0.x - mu) * rs * ga0.x + be0.x + y0.x;
                    h0.y = (y0.y - mu) * rs * ga0.y + be0.y + y0.y;
                    h0.z = (y0.z - mu) * rs * ga0.z + be0.z + y0.z;
                    h0.w = (y0.w - mu) * rs * ga0.w + be0.w + y0.w;
                    h1.x = (y1.x - mu) * rs * ga1.x + be1.x + y1.x;
                    h1.y = (y1.y - mu) * rs * ga1.y + be1.y + y1.y;
                    h1.z = (y1.z - mu) * rs * ga1.z + be1.z + y1.z;
                    h1.w = (y1.w - mu) * rs * ga1.w + be1.w + y1.w;
                    *(float4*)&sm[b * 132 + k8]     = h0;
                    *(float4*)&sm[b * 132 + k8 + 4] = h1;
                    if (jt == 0) {
                        float* op = out + ((size_t)b * TT + (t - 1)) * CC + c;
                        *(float4*)(op)     = h0;
                        *(float4*)(op + 4) = h1;
                    }
                } else {
                    float4 z4 = make_float4(0.f, 0.f, 0.f, 0.f);
                    *(float4*)&sm[b * 132 + k8]     = z4;
                    *(float4*)&sm[b * 132 + k8 + 4] = z4;
                }
            } else {
                const float* p = x + ((size_t)b * TT + t) * CC + (kc - 8) * 128 + k8;
                *(float4*)&sm[b * 132 + k8]     = *(const float4*)p;
                *(float4*)&sm[b * 132 + k8 + 4] = *(const float4*)(p + 4);
            }
            float acc[4][4];
#pragma unroll
            for (int a = 0; a < 4; a++)
#pragma unroll
                for (int c2 = 0; c2 < 4; c2++) acc[a][c2] = 0.0f;
            gemm_core<4, 132>(Wa + (size_t)(jt * 256) * 2048 + kc * 128,
                              sm, acc, tid, tx, ty);
            const int jb = jt * 256 + ty * 4;
#pragma unroll
            for (int jj = 0; jj < 4; jj++)
#pragma unroll
                for (int q = 0; q < 4; q++)
                    g_yp[kc][(jb + jj) * 32 + tx + 8 * q] = acc[jj][q];
        }
        gbar();

        // ===== Phase C: gelu(reduce)+fill, GEMM2 partial (4 nt x 32 kc2) =====
        {
            const int nt = bid & 3, kc2 = bid >> 2;
            const int j0 = kc2 * 64;
            for (int i = tid; i < 64 * 32; i += 512) {
                int j = i >> 5, b2 = i & 31;
                float v = ba[j0 + j];
#pragma unroll
                for (int p = 0; p < 16; p++)
                    v += __ldcg(&g_yp[p][(j0 + j) * 32 + b2]);
                v = 0.5f * v * (1.0f + erff(v * 0.70710678118654752440f));
                sm[b2 * 68 + j] = v;
            }
            float acc[4][4];
#pragma unroll
            for (int a = 0; a < 4; a++)
#pragma unroll
                for (int c2 = 0; c2 < 4; c2++) acc[a][c2] = 0.0f;
            gemm_core<2, 68>(Wb + (size_t)(nt * 256) * 2048 + j0,
                             sm, acc, tid, tx, ty);
            const int n0 = nt * 256 + ty * 4;
#pragma unroll
            for (int q = 0; q < 4; q++) {
                float4 v = make_float4(acc[0][q], acc[1][q], acc[2][q], acc[3][q]);
                *(float4*)&g_y2p[kc2][(tx + 8 * q) * 1024 + n0] = v;
            }
        }
        gbar();

        // ===== Phase D1: parallel reduce + LN statistics (128 blocks: b x quarter) ===
        {
            const int b = bid & 31, q = bid >> 5;
            float v = 0.0f;
            if (tid < 256) {
                const int n = q * 256 + tid;
                v = bb[n];
#pragma unroll
                for (int p = 0; p < 32; p++)
                    v += __ldcg(&g_y2p[p][b * 1024 + n]);
                g_y2[b * 1024 + n] = v;
            }
            float s = v, s2 = v * v;
            for (int o = 16; o; o >>= 1) {
                s  += __shfl_xor_sync(~0u, s, o);
                s2 += __shfl_xor_sync(~0u, s2, o);
            }
            if ((tid & 31) == 0) { red1[tid >> 5] = s; red2[tid >> 5] = s2; }
            __syncthreads();
            if (tid == 0) {
                float ts = 0.0f, ts2 = 0.0f;
#pragma unroll
                for (int w = 0; w < 16; w++) { ts += red1[w]; ts2 += red2[w]; }
                g_sum[b][q] = ts;
                g_sq[b][q] = ts2;
            }
        }
        gbar();
    }

    // ===== Epilogue: out[:, T-1, :] =====
    if (bid < 8) {
        const int kc = bid;
        if (tid < 32) {
            float s = 0.0f, s2 = 0.0f;
#pragma unroll
            for (int q = 0; q < 4; q++) {
                s  += __ldcg(&g_sum[tid][q]);
                s2 += __ldcg(&g_sq[tid][q]);
            }
            float mu = s * (1.0f / 1024.0f);
            float var = s2 * (1.0f / 1024.0f) - mu * mu;
            smu[tid] = mu;
            srs[tid] = rsqrtf(var + 1e-5f);
        }
        __syncthreads();
        const int b = tid >> 4, k8 = (tid & 15) * 8;
        const int c = kc * 128 + k8;
        const float mu = smu[b], rs = srs[b];
        float4 y0 = __ldcg((const float4*)&g_y2[b * CC + c]);
        float4 y1 = __ldcg((const float4*)&g_y2[b * CC + c + 4]);
        float4 ga0 = *(const float4*)(gamma + c);
        float4 ga1 = *(const float4*)(gamma + c + 4);
        float4 be0 = *(const float4*)(beta + c);
        float4 be1 = *(const float4*)(beta + c + 4);
        float4 h0, h1;
        h0.x = (y0.x - mu) * rs * ga0.x + be0.x + y0.x;
        h0.y = (y0.y - mu) * rs * ga0.y + be0.y + y0.y;
        h0.z = (y0.z - mu) * rs * ga0.z + be0.z + y0.z;
        h0.w = (y0.w - mu) * rs * ga0.w + be0.w + y0.w;
        h1.x = (y1.x - mu) * rs * ga1.x + be1.x + y1.x;
        h1.y = (y1.y - mu) * rs * ga1.y + be1.y + y1.y;
        h1.z = (y1.z - mu) * rs * ga1.z + be1.z + y1.z;
        h1.w = (y1.w - mu) * rs * ga1.w + be1.w + y1.w;
        float* op = out + ((size_t)b * TT + (TT - 1)) * CC + c;
        *(float4*)(op)     = h0;
        *(float4*)(op + 4) = h1;
    }
}

extern "C" void kernel_launch(void* const* d_in, const int* in_sizes, int n_in,
                              void* d_out, int out_size) {
    const float* x     = (const float*)d_in[0];
    const float* Wa    = (const float*)d_in[1];
    const float* ba    = (const float*)d_in[2];
    const float* Wb    = (const float*)d_in[3];
    const float* bb    = (const float*)d_in[4];
    const float* gamma = (const float*)d_in[5];
    const float* beta  = (const float*)d_in[6];
    float* out = (float*)d_out;

    const int smem = SMEM_FLOATS * 4;   // 84480 B
    cudaFuncSetAttribute(k_main, cudaFuncAttributeMaxDynamicSharedMemorySize, smem);
    k_main<<<NBLK, 512, smem>>>(x, Wa, ba, Wb, bb, gamma, beta, out);
}